// round 1
// baseline (speedup 1.0000x reference)
#include <cuda_runtime.h>
#include <cstdint>

// ---------------------------------------------------------------------------
// Problem constants (from reference): D=9, E=2, H=128, M=32, O=2, k=1.
// gates are one-hot argmax (softmax of a single top-1 logit == 1.0).
// Fold W2@Wout -> Wf[E][128][2], b2@Wout + bout -> bf[E][2].
// out[n] = relu(x[n] @ W1[e] + b1[e]) @ Wf[e] + bf[e],  e = argmax(x @ w_gate)
// loss = 2 * cv^2(counts) * 0.01,  cv^2 = ((c0-c1)^2/2) / ((N/2)^2 + 1e-10)
// ---------------------------------------------------------------------------

// Packed weight blob: [e][jp][slot] with jp = hidden-pair index (0..63),
// slot 0..11 as float2: slots 0..8 = {W1[e][d][2jp], W1[e][d][2jp+1]},
// slot 9 = Wf pair (o=0), slot 10 = Wf pair (o=1), slot 11 = b1 pair.
__device__ __align__(16) float2 g_blob[2 * 64 * 12];
__device__ float g_bf[4];
__device__ int   g_count;

// ---------------- packed f32x2 helpers (sm_103a) ----------------
__device__ __forceinline__ unsigned long long fma2(unsigned long long a,
                                                   unsigned long long b,
                                                   unsigned long long c) {
    unsigned long long d;
    asm("fma.rn.f32x2 %0, %1, %2, %3;" : "=l"(d) : "l"(a), "l"(b), "l"(c));
    return d;
}

__device__ __forceinline__ unsigned long long pack_dup(float v) {
    unsigned long long r;
    asm("mov.b64 %0, {%1, %1};" : "=l"(r) : "f"(v));
    return r;
}

__device__ __forceinline__ unsigned long long relu2(unsigned long long h) {
    float lo, hi;
    asm("mov.b64 {%0, %1}, %2;" : "=f"(lo), "=f"(hi) : "l"(h));
    lo = fmaxf(lo, 0.0f);
    hi = fmaxf(hi, 0.0f);
    unsigned long long r;
    asm("mov.b64 %0, {%1, %2};" : "=l"(r) : "f"(lo), "f"(hi));
    return r;
}

__device__ __forceinline__ float hsum2(unsigned long long h) {
    float lo, hi;
    asm("mov.b64 {%0, %1}, %2;" : "=f"(lo), "=f"(hi) : "l"(h));
    return lo + hi;
}

// ---------------------------------------------------------------------------
// Fold kernel: builds g_blob, g_bf, zeros g_count. 1541 work items.
// ---------------------------------------------------------------------------
__global__ void fold_kernel(const float* __restrict__ W1,
                            const float* __restrict__ b1,
                            const float* __restrict__ W2,
                            const float* __restrict__ b2,
                            const float* __restrict__ Wout,
                            const float* __restrict__ bout) {
    int idx = blockIdx.x * 256 + threadIdx.x;
    if (idx < 1536) {
        int slot = idx % 12;
        int jp   = (idx / 12) & 63;
        int e    = idx / 768;
        int j0 = jp * 2, j1 = j0 + 1;
        float a, b;
        if (slot < 9) {
            // W1: [E, D, H] -> element (e, d=slot, j)
            a = W1[(e * 9 + slot) * 128 + j0];
            b = W1[(e * 9 + slot) * 128 + j1];
        } else if (slot < 11) {
            int o = slot - 9;
            float s0 = 0.0f, s1 = 0.0f;
            #pragma unroll
            for (int m = 0; m < 32; ++m) {
                float wo = Wout[m * 2 + o];
                s0 = fmaf(W2[(e * 128 + j0) * 32 + m], wo, s0);
                s1 = fmaf(W2[(e * 128 + j1) * 32 + m], wo, s1);
            }
            a = s0; b = s1;
        } else {
            a = b1[e * 128 + j0];
            b = b1[e * 128 + j1];
        }
        g_blob[idx] = make_float2(a, b);
    } else if (idx < 1540) {
        int q = idx - 1536;
        int e = q >> 1, o = q & 1;
        float s = bout[o];
        #pragma unroll
        for (int m = 0; m < 32; ++m)
            s = fmaf(b2[e * 32 + m], Wout[m * 2 + o], s);
        g_bf[q] = s;
    } else if (idx == 1540) {
        g_count = 0;
    }
}

// ---------------------------------------------------------------------------
// Main kernel: 256 threads/block, 2 tokens/thread (512 tokens per block).
// Shared weight layout: expert 0 at float4 index 0..383, 16B skew, expert 1
// at 385..768 (skew keeps 2-address LDS.128 broadcasts on disjoint banks).
// ---------------------------------------------------------------------------
__global__ void __launch_bounds__(256) moe_main(const float* __restrict__ x,
                                                const float* __restrict__ wg,
                                                float* __restrict__ out,
                                                int N) {
    __shared__ float4 sw4[776];
    {
        const float4* blob4 = reinterpret_cast<const float4*>(g_blob);
        for (int i = threadIdx.x; i < 768; i += 256) {
            int di = (i < 384) ? i : (i + 1);
            sw4[di] = blob4[i];
        }
    }
    __syncthreads();

    const int t0  = blockIdx.x * 512 + threadIdx.x;
    const int t1  = t0 + 256;
    const bool ok0 = (t0 < N);
    const bool ok1 = (t1 < N);

    // gating weights (uniform -> broadcast loads)
    float wgr[18];
    #pragma unroll
    for (int i = 0; i < 18; ++i) wgr[i] = wg[i];

    unsigned long long xd0[9], xd1[9];
    int rb0, rb1, e0, e1;
    {
        float l0 = 0.0f, l1 = 0.0f;
        const float* xr = x + (size_t)t0 * 9;
        #pragma unroll
        for (int d = 0; d < 9; ++d) {
            float v = ok0 ? xr[d] : 0.0f;
            l0 = fmaf(v, wgr[2 * d], l0);
            l1 = fmaf(v, wgr[2 * d + 1], l1);
            xd0[d] = pack_dup(v);
        }
        e0  = (l1 > l0) ? 1 : 0;
        rb0 = e0 ? 385 : 0;
    }
    {
        float l0 = 0.0f, l1 = 0.0f;
        const float* xr = x + (size_t)t1 * 9;
        #pragma unroll
        for (int d = 0; d < 9; ++d) {
            float v = ok1 ? xr[d] : 0.0f;
            l0 = fmaf(v, wgr[2 * d], l0);
            l1 = fmaf(v, wgr[2 * d + 1], l1);
            xd1[d] = pack_dup(v);
        }
        e1  = (l1 > l0) ? 1 : 0;
        rb1 = e1 ? 385 : 0;
    }

    // expert-1 assignment count (for load-balancing loss)
    unsigned bal0 = __ballot_sync(0xffffffffu, (e0 != 0) && ok0);
    unsigned bal1 = __ballot_sync(0xffffffffu, (e1 != 0) && ok1);
    if ((threadIdx.x & 31) == 0) {
        int c = __popc(bal0) + __popc(bal1);
        if (c) atomicAdd(&g_count, c);
    }

    unsigned long long a00 = 0ull, a01 = 0ull, a10 = 0ull, a11 = 0ull;
    const longlong2* sll = reinterpret_cast<const longlong2*>(sw4);

    #pragma unroll 2
    for (int jp = 0; jp < 64; ++jp) {
        {   // token 0
            const longlong2* row = sll + rb0 + jp * 6;
            longlong2 r0 = row[0], r1 = row[1], r2 = row[2];
            longlong2 r3 = row[3], r4 = row[4], r5 = row[5];
            unsigned long long h = (unsigned long long)r5.y;   // b1 pair
            h = fma2(xd0[0], (unsigned long long)r0.x, h);
            h = fma2(xd0[1], (unsigned long long)r0.y, h);
            h = fma2(xd0[2], (unsigned long long)r1.x, h);
            h = fma2(xd0[3], (unsigned long long)r1.y, h);
            h = fma2(xd0[4], (unsigned long long)r2.x, h);
            h = fma2(xd0[5], (unsigned long long)r2.y, h);
            h = fma2(xd0[6], (unsigned long long)r3.x, h);
            h = fma2(xd0[7], (unsigned long long)r3.y, h);
            h = fma2(xd0[8], (unsigned long long)r4.x, h);
            h = relu2(h);
            a00 = fma2(h, (unsigned long long)r4.y, a00);      // Wf o=0
            a01 = fma2(h, (unsigned long long)r5.x, a01);      // Wf o=1
        }
        {   // token 1
            const longlong2* row = sll + rb1 + jp * 6;
            longlong2 r0 = row[0], r1 = row[1], r2 = row[2];
            longlong2 r3 = row[3], r4 = row[4], r5 = row[5];
            unsigned long long h = (unsigned long long)r5.y;
            h = fma2(xd1[0], (unsigned long long)r0.x, h);
            h = fma2(xd1[1], (unsigned long long)r0.y, h);
            h = fma2(xd1[2], (unsigned long long)r1.x, h);
            h = fma2(xd1[3], (unsigned long long)r1.y, h);
            h = fma2(xd1[4], (unsigned long long)r2.x, h);
            h = fma2(xd1[5], (unsigned long long)r2.y, h);
            h = fma2(xd1[6], (unsigned long long)r3.x, h);
            h = fma2(xd1[7], (unsigned long long)r3.y, h);
            h = fma2(xd1[8], (unsigned long long)r4.x, h);
            h = relu2(h);
            a10 = fma2(h, (unsigned long long)r4.y, a10);
            a11 = fma2(h, (unsigned long long)r5.x, a11);
        }
    }

    if (ok0) {
        float2 o;
        o.x = hsum2(a00) + g_bf[e0 * 2 + 0];
        o.y = hsum2(a01) + g_bf[e0 * 2 + 1];
        reinterpret_cast<float2*>(out)[t0] = o;
    }
    if (ok1) {
        float2 o;
        o.x = hsum2(a10) + g_bf[e1 * 2 + 0];
        o.y = hsum2(a11) + g_bf[e1 * 2 + 1];
        reinterpret_cast<float2*>(out)[t1] = o;
    }
}

// ---------------------------------------------------------------------------
// Loss kernel: closed-form cv^2 from the expert-1 count.
// ---------------------------------------------------------------------------
__global__ void loss_kernel(float* __restrict__ out, int N, int out_size) {
    if (out_size > 2 * N) {
        double c1   = (double)g_count;
        double c0   = (double)N - c1;
        double mean = 0.5 * (c0 + c1);
        double d    = c0 - c1;
        double cv   = (0.5 * d * d) / (mean * mean + 1e-10);
        out[out_size - 1] = (float)(0.02 * cv);   // (cv_imp + cv_load) * 0.01
    }
}

// ---------------------------------------------------------------------------
// Launch. Input order (metadata): num_prop, cat_prop, w_gate, W1, b1, W2, b2,
// Wout, bout, k.
// ---------------------------------------------------------------------------
extern "C" void kernel_launch(void* const* d_in, const int* in_sizes, int n_in,
                              void* d_out, int out_size) {
    const float* x    = (const float*)d_in[0];
    const float* wg   = (const float*)d_in[2];
    const float* W1   = (const float*)d_in[3];
    const float* b1   = (const float*)d_in[4];
    const float* W2   = (const float*)d_in[5];
    const float* b2   = (const float*)d_in[6];
    const float* Wout = (const float*)d_in[7];
    const float* bout = (const float*)d_in[8];
    float* out = (float*)d_out;

    int N = in_sizes[0] / 9;

    fold_kernel<<<7, 256>>>(W1, b1, W2, b2, Wout, bout);
    int blocks = (N + 511) / 512;
    moe_main<<<blocks, 256>>>(x, wg, out, N);
    loss_kernel<<<1, 1>>>(out, N, out_size);
}